// round 6
// baseline (speedup 1.0000x reference)
#include <cuda_runtime.h>
#include <math.h>

#define B_  4
#define C_  2
#define H_  2048
#define W_  128
#define HP  2050
#define WP  130
#define NPIX (B_*128*128)

// Scratch: padded NHWC x = concat([sar, fs]) as float4 per pixel (c fastest).
__device__ float4 g_xpad4[(size_t)B_*HP*WP];
// fm: [b][c][k(128)][w(128)]
__device__ float  g_fm[B_*2*128*128];

// ---------------------------------------------------------------------------
// Kernel Z: zero the padding border of g_xpad4
// ---------------------------------------------------------------------------
__global__ void border_kernel() {
    int i = blockIdx.x * blockDim.x + threadIdx.x;
    const int perb = 2 * WP + 2 * HP;       // 4360
    if (i >= B_ * perb) return;
    int b = i / perb;
    int r = i % perb;
    float4 z = make_float4(0.f, 0.f, 0.f, 0.f);
    size_t base = (size_t)b * HP * WP;
    if (r < WP)            g_xpad4[base + r] = z;
    else if (r < 2 * WP)   g_xpad4[base + (size_t)(HP - 1) * WP + (r - WP)] = z;
    else {
        int rr = r - 2 * WP;
        int y = rr >> 1;
        int x = (rr & 1) ? (WP - 1) : 0;
        g_xpad4[base + (size_t)y * WP + x] = z;
    }
}

// ---------------------------------------------------------------------------
// Kernel A: adaptive avg pool + 1x1 conv + sigmoid
// ---------------------------------------------------------------------------
__global__ void fm_kernel(const float* __restrict__ rgb,
                          const float* __restrict__ w_fm) {
    int idx = blockIdx.x * blockDim.x + threadIdx.x;
    if (idx >= NPIX) return;
    int b   = idx >> 14;
    int rem = idx & 16383;
    int ph  = rem >> 7;
    int pw  = rem & 127;
    const float* p0 = rgb + ((size_t)(b * 2 + 0) * H_ + ph * 16) * W_ + pw;
    const float* p1 = rgb + ((size_t)(b * 2 + 1) * H_ + ph * 16) * W_ + pw;
    float a0 = 0.f, a1 = 0.f;
#pragma unroll
    for (int r = 0; r < 16; r++) { a0 += p0[r * W_]; a1 += p1[r * W_]; }
    a0 *= 0.0625f; a1 *= 0.0625f;
    float z0 = w_fm[0] * a0 + w_fm[1] * a1;
    float z1 = w_fm[2] * a0 + w_fm[3] * a1;
    g_fm[(b * 2 + 0) * 16384 + rem] = 1.f / (1.f + expf(-z0));
    g_fm[(b * 2 + 1) * 16384 + rem] = 1.f / (1.f + expf(-z1));
}

// ---------------------------------------------------------------------------
// Kernel B v3: register-tiled GEMM, A-tile rows 16B-aligned (R_PAD=72),
// A loaded via LDS.128 (2 per c per kk) instead of 8 scalar LDS.
// ---------------------------------------------------------------------------
#define KT     16
#define R_PAD  72
__global__ void __launch_bounds__(256)
fs_kernel(const float* __restrict__ rgb, const float* __restrict__ sar,
          const float* __restrict__ w_fs) {
    extern __shared__ float sm[];
    float* fm_s = sm;                    // [c][k][wt] : 16384 floats
    float* a_s  = sm + 16384;            // [c][kk][R_PAD] : 2*16*72 floats

    int b   = blockIdx.z;
    int wh  = blockIdx.y;
    int h0  = blockIdx.x * 64;
    int tid = threadIdx.x;
    int rgrp = tid & 7;
    int wgrp = tid >> 3;
    int rb  = rgrp * 8;                  // multiple of 8 -> float4 aligned
    int wt0 = wgrp * 2;

    {
        const float4* src = (const float4*)(g_fm + (size_t)b * 32768);
        float4* dst = (float4*)fm_s;
        for (int i = tid; i < 4096; i += 256) {
            int wt4 = i & 15;
            int k   = (i >> 4) & 127;
            int c   = i >> 11;
            dst[i] = src[(size_t)c * 4096 + k * 32 + wh * 16 + wt4];
        }
    }

    float acc[8][2][2];
#pragma unroll
    for (int i = 0; i < 8; i++)
#pragma unroll
        for (int j = 0; j < 2; j++) { acc[i][j][0] = 0.f; acc[i][j][1] = 0.f; }

    const float* rgb_b0 = rgb + (size_t)(b * 2 + 0) * H_ * W_;
    const float* rgb_b1 = rgb + (size_t)(b * 2 + 1) * H_ * W_;

    for (int k0 = 0; k0 < 128; k0 += KT) {
        __syncthreads();
        for (int i = tid; i < 2048; i += 256) {
            int kk = i & 15;
            int r  = (i >> 4) & 63;
            int c  = i >> 10;
            const float* src = c ? rgb_b1 : rgb_b0;
            a_s[c * (KT * R_PAD) + kk * R_PAD + r] =
                src[(size_t)(h0 + r) * W_ + k0 + kk];
        }
        __syncthreads();

#pragma unroll
        for (int kk = 0; kk < KT; kk++) {
            int k = k0 + kk;
            float2 b0 = *(const float2*)(fm_s + 0 * 8192 + k * 64 + wt0);
            float2 b1 = *(const float2*)(fm_s + 1 * 8192 + k * 64 + wt0);
            const float4* a0p =
                (const float4*)(a_s + 0 * (KT * R_PAD) + kk * R_PAD + rb);
            const float4* a1p =
                (const float4*)(a_s + 1 * (KT * R_PAD) + kk * R_PAD + rb);
            float4 a0lo = a0p[0], a0hi = a0p[1];
            float4 a1lo = a1p[0], a1hi = a1p[1];
            float a0v[8] = {a0lo.x, a0lo.y, a0lo.z, a0lo.w,
                            a0hi.x, a0hi.y, a0hi.z, a0hi.w};
            float a1v[8] = {a1lo.x, a1lo.y, a1lo.z, a1lo.w,
                            a1hi.x, a1hi.y, a1hi.z, a1hi.w};
#pragma unroll
            for (int i = 0; i < 8; i++) {
                acc[i][0][0] = fmaf(a0v[i], b0.x, acc[i][0][0]);
                acc[i][1][0] = fmaf(a0v[i], b0.y, acc[i][1][0]);
                acc[i][0][1] = fmaf(a1v[i], b1.x, acc[i][0][1]);
                acc[i][1][1] = fmaf(a1v[i], b1.y, acc[i][1][1]);
            }
        }
    }

    float w00 = w_fs[0], w01 = w_fs[1], w10 = w_fs[2], w11 = w_fs[3];
    const float* sar_b0 = sar + (size_t)(b * 2 + 0) * H_ * W_;
    const float* sar_b1 = sar + (size_t)(b * 2 + 1) * H_ * W_;
#pragma unroll
    for (int i = 0; i < 8; i++) {
        int h = h0 + rb + i;
#pragma unroll
        for (int j = 0; j < 2; j++) {
            int w = wh * 64 + wt0 + j;
            size_t off = (size_t)h * W_ + w;
            float m0 = acc[i][j][0] + rgb_b0[off];
            float m1 = acc[i][j][1] + rgb_b1[off];
            float fs0 = w00 * m0 + w01 * m1;
            float fs1 = w10 * m0 + w11 * m1;
            g_xpad4[((size_t)b * HP + (h + 1)) * WP + (w + 1)] =
                make_float4(sar_b0[off], sar_b1[off], fs0, fs1);
        }
    }
}

// ---------------------------------------------------------------------------
// Kernel C v5: 2 pixels per thread (vertical pair). Block 256 = 128x * 2 ygrp,
// 4 rows/block, grid (H/4, B). Weight LDS amortized 2x, vertical tap sharing.
// launch_bounds(256,3): <=85 regs -> 24 warps/SM.
// ---------------------------------------------------------------------------
__global__ void __launch_bounds__(256, 3)
deform_kernel(const float* __restrict__ wp, const float* __restrict__ bp,
              const float* __restrict__ wdc, float* __restrict__ out) {
    __shared__ float4 s_tile[6 * WP];     // padded rows h0..h0+5
    __shared__ float4 s_wp4[9 * 18];      // [tap][j] float4 over c_in
    __shared__ float4 s_wdc4[2 * 9];      // [o][n]   float4 over c_in
    __shared__ float  s_bp[18];

    int h0 = blockIdx.x * 4;
    int b  = blockIdx.y;
    int t  = threadIdx.x;

    if (t < 18) s_bp[t] = bp[t];
    for (int i = t; i < 9 * 18 * 4; i += 256) {
        int c = i & 3, rest = i >> 2;
        int j = rest % 18, tap = rest / 18;
        ((float*)s_wp4)[i] = wp[(j * 4 + c) * 9 + tap];
    }
    for (int i = t; i < 2 * 9 * 4; i += 256) {
        int c = i & 3, rest = i >> 2;
        int n = rest % 9, o = rest / 9;
        ((float*)s_wdc4)[i] = wdc[(o * 4 + c) * 9 + n];
    }
    const float4* base = g_xpad4 + (size_t)b * HP * WP;
    for (int i = t; i < 6 * WP; i += 256) {
        int ry = i / WP, x = i - ry * WP;
        s_tile[i] = base[(size_t)(h0 + ry) * WP + x];
    }
    __syncthreads();

    int lane = t & 31;
    int wid  = t >> 5;
    int xc   = (wid & 3) * 32 + lane;   // x in 0..127 (lanes consecutive in x)
    int yg   = wid >> 2;                // 0/1 row-pair group
    int rgb2 = yg * 2;                  // first tile row of this thread's pair

    // ---- offset conv for 2 vertical pixels; off[p][0..8]=dy, [9..17]=dx ----
    float off[2][18];
#pragma unroll
    for (int p = 0; p < 2; p++)
#pragma unroll
        for (int j = 0; j < 18; j++) off[p][j] = s_bp[j];

#pragma unroll
    for (int kx = 0; kx < 3; kx++) {
        float4 v[4];
#pragma unroll
        for (int q = 0; q < 4; q++)
            v[q] = s_tile[(rgb2 + q) * WP + xc + kx];
#pragma unroll
        for (int ky = 0; ky < 3; ky++) {
            const float4* wr = s_wp4 + (ky * 3 + kx) * 18;
#pragma unroll
            for (int j = 0; j < 18; j++) {
                float4 u = wr[j];
#pragma unroll
                for (int p = 0; p < 2; p++) {
                    float4 vv = v[p + ky];
                    off[p][j] += vv.x * u.x + vv.y * u.y + vv.z * u.z + vv.w * u.w;
                }
            }
        }
    }

    // ---- bilinear sampling + deform-conv reduce, per pixel ----
    float pxb = (float)(xc + 1);
    float* out_b0 = out + (size_t)(b * 2 + 0) * H_ * W_ + xc;
    float* out_b1 = out + (size_t)(b * 2 + 1) * H_ * W_ + xc;
#pragma unroll
    for (int p = 0; p < 2; p++) {
        int h = h0 + rgb2 + p;
        float pyb = (float)(h + 1);
        float acc0 = 0.f, acc1 = 0.f;
#pragma unroll
        for (int n = 0; n < 9; n++) {
            float py = pyb + (float)(n / 3 - 1) + off[p][n];
            float px = pxb + (float)(n % 3 - 1) + off[p][9 + n];
            float fy = floorf(py), fx = floorf(px);
            float y0f = fminf(fmaxf(fy,        0.f), (float)(HP - 1));
            float y1f = fminf(fmaxf(fy + 1.f,  0.f), (float)(HP - 1));
            float x0f = fminf(fmaxf(fx,        0.f), (float)(WP - 1));
            float x1f = fminf(fmaxf(fx + 1.f,  0.f), (float)(WP - 1));
            int y0 = (int)y0f, y1 = (int)y1f, x0 = (int)x0f, x1 = (int)x1f;
            float pyc = fminf(fmaxf(py, 0.f), (float)(HP - 1));
            float pxc = fminf(fmaxf(px, 0.f), (float)(WP - 1));
            float wy0 = 1.f + (y0f - pyc);
            float wy1 = 1.f - (y1f - pyc);
            float wx0 = 1.f + (x0f - pxc);
            float wx1 = 1.f - (x1f - pxc);
            float glt = wy0 * wx0, grb = wy1 * wx1;
            float glb = wy0 * wx1, grt = wy1 * wx0;

            float4 vlt = base[(size_t)y0 * WP + x0];
            float4 vrb = base[(size_t)y1 * WP + x1];
            float4 vlb = base[(size_t)y0 * WP + x1];
            float4 vrt = base[(size_t)y1 * WP + x0];

            float4 s;
            s.x = glt * vlt.x + grb * vrb.x + glb * vlb.x + grt * vrt.x;
            s.y = glt * vlt.y + grb * vrb.y + glb * vlb.y + grt * vrt.y;
            s.z = glt * vlt.z + grb * vrb.z + glb * vlb.z + grt * vrt.z;
            s.w = glt * vlt.w + grb * vrb.w + glb * vlb.w + grt * vrt.w;

            float4 wa = s_wdc4[n];
            float4 wb = s_wdc4[9 + n];
            acc0 += s.x * wa.x + s.y * wa.y + s.z * wa.z + s.w * wa.w;
            acc1 += s.x * wb.x + s.y * wb.y + s.z * wb.z + s.w * wb.w;
        }
        out_b0[(size_t)h * W_] = acc0;
        out_b1[(size_t)h * W_] = acc1;
    }
}

// ---------------------------------------------------------------------------
extern "C" void kernel_launch(void* const* d_in, const int* in_sizes, int n_in,
                              void* d_out, int out_size) {
    const float* rgb  = (const float*)d_in[0];
    const float* sar  = (const float*)d_in[1];
    const float* w_fm = (const float*)d_in[2];
    const float* w_fs = (const float*)d_in[3];
    const float* w_p  = (const float*)d_in[4];
    const float* b_p  = (const float*)d_in[5];
    const float* w_dc = (const float*)d_in[6];
    float* out = (float*)d_out;

    {
        int total = B_ * (2 * WP + 2 * HP);
        border_kernel<<<(total + 255) / 256, 256>>>();
    }
    fm_kernel<<<(NPIX + 255) / 256, 256>>>(rgb, w_fm);
    {
        int smem = (16384 + 2 * KT * R_PAD) * (int)sizeof(float);
        cudaFuncSetAttribute(fs_kernel,
                             cudaFuncAttributeMaxDynamicSharedMemorySize, smem);
        dim3 grid(H_ / 64, 2, B_);
        fs_kernel<<<grid, 256, smem>>>(rgb, sar, w_fs);
    }
    {
        dim3 grid(H_ / 4, B_);
        deform_kernel<<<grid, 256>>>(w_p, b_p, w_dc, out);
    }
}

// round 14
// speedup vs baseline: 1.0783x; 1.0783x over previous
#include <cuda_runtime.h>
#include <math.h>

#define B_  4
#define C_  2
#define H_  2048
#define W_  128
#define HP  2050
#define WP  130
#define NPIX (B_*128*128)

// Scratch: padded NHWC x = concat([sar, fs]) as float4 per pixel (c fastest).
__device__ float4 g_xpad4[(size_t)B_*HP*WP];
// fm: [b][c][k(128)][w(128)]
__device__ float  g_fm[B_*2*128*128];

// ---------------------------------------------------------------------------
// Kernel Z: zero the padding border of g_xpad4
// ---------------------------------------------------------------------------
__global__ void border_kernel() {
    int i = blockIdx.x * blockDim.x + threadIdx.x;
    const int perb = 2 * WP + 2 * HP;       // 4360
    if (i >= B_ * perb) return;
    int b = i / perb;
    int r = i % perb;
    float4 z = make_float4(0.f, 0.f, 0.f, 0.f);
    size_t base = (size_t)b * HP * WP;
    if (r < WP)            g_xpad4[base + r] = z;
    else if (r < 2 * WP)   g_xpad4[base + (size_t)(HP - 1) * WP + (r - WP)] = z;
    else {
        int rr = r - 2 * WP;
        int y = rr >> 1;
        int x = (rr & 1) ? (WP - 1) : 0;
        g_xpad4[base + (size_t)y * WP + x] = z;
    }
}

// ---------------------------------------------------------------------------
// Kernel A: adaptive avg pool + 1x1 conv + sigmoid
// ---------------------------------------------------------------------------
__global__ void fm_kernel(const float* __restrict__ rgb,
                          const float* __restrict__ w_fm) {
    int idx = blockIdx.x * blockDim.x + threadIdx.x;
    if (idx >= NPIX) return;
    int b   = idx >> 14;
    int rem = idx & 16383;
    int ph  = rem >> 7;
    int pw  = rem & 127;
    const float* p0 = rgb + ((size_t)(b * 2 + 0) * H_ + ph * 16) * W_ + pw;
    const float* p1 = rgb + ((size_t)(b * 2 + 1) * H_ + ph * 16) * W_ + pw;
    float a0 = 0.f, a1 = 0.f;
#pragma unroll
    for (int r = 0; r < 16; r++) { a0 += p0[r * W_]; a1 += p1[r * W_]; }
    a0 *= 0.0625f; a1 *= 0.0625f;
    float z0 = w_fm[0] * a0 + w_fm[1] * a1;
    float z1 = w_fm[2] * a0 + w_fm[3] * a1;
    g_fm[(b * 2 + 0) * 16384 + rem] = 1.f / (1.f + expf(-z0));
    g_fm[(b * 2 + 1) * 16384 + rem] = 1.f / (1.f + expf(-z1));
}

// ---------------------------------------------------------------------------
// Kernel B v3: register-tiled GEMM, A-tile rows 16B-aligned (R_PAD=72),
// A loaded via LDS.128 (2 per c per kk).
// ---------------------------------------------------------------------------
#define KT     16
#define R_PAD  72
__global__ void __launch_bounds__(256)
fs_kernel(const float* __restrict__ rgb, const float* __restrict__ sar,
          const float* __restrict__ w_fs) {
    extern __shared__ float sm[];
    float* fm_s = sm;                    // [c][k][wt] : 16384 floats
    float* a_s  = sm + 16384;            // [c][kk][R_PAD]

    int b   = blockIdx.z;
    int wh  = blockIdx.y;
    int h0  = blockIdx.x * 64;
    int tid = threadIdx.x;
    int rgrp = tid & 7;
    int wgrp = tid >> 3;
    int rb  = rgrp * 8;
    int wt0 = wgrp * 2;

    {
        const float4* src = (const float4*)(g_fm + (size_t)b * 32768);
        float4* dst = (float4*)fm_s;
        for (int i = tid; i < 4096; i += 256) {
            int wt4 = i & 15;
            int k   = (i >> 4) & 127;
            int c   = i >> 11;
            dst[i] = src[(size_t)c * 4096 + k * 32 + wh * 16 + wt4];
        }
    }

    float acc[8][2][2];
#pragma unroll
    for (int i = 0; i < 8; i++)
#pragma unroll
        for (int j = 0; j < 2; j++) { acc[i][j][0] = 0.f; acc[i][j][1] = 0.f; }

    const float* rgb_b0 = rgb + (size_t)(b * 2 + 0) * H_ * W_;
    const float* rgb_b1 = rgb + (size_t)(b * 2 + 1) * H_ * W_;

    for (int k0 = 0; k0 < 128; k0 += KT) {
        __syncthreads();
        for (int i = tid; i < 2048; i += 256) {
            int kk = i & 15;
            int r  = (i >> 4) & 63;
            int c  = i >> 10;
            const float* src = c ? rgb_b1 : rgb_b0;
            a_s[c * (KT * R_PAD) + kk * R_PAD + r] =
                src[(size_t)(h0 + r) * W_ + k0 + kk];
        }
        __syncthreads();

#pragma unroll
        for (int kk = 0; kk < KT; kk++) {
            int k = k0 + kk;
            float2 b0 = *(const float2*)(fm_s + 0 * 8192 + k * 64 + wt0);
            float2 b1 = *(const float2*)(fm_s + 1 * 8192 + k * 64 + wt0);
            const float4* a0p =
                (const float4*)(a_s + 0 * (KT * R_PAD) + kk * R_PAD + rb);
            const float4* a1p =
                (const float4*)(a_s + 1 * (KT * R_PAD) + kk * R_PAD + rb);
            float4 a0lo = a0p[0], a0hi = a0p[1];
            float4 a1lo = a1p[0], a1hi = a1p[1];
            float a0v[8] = {a0lo.x, a0lo.y, a0lo.z, a0lo.w,
                            a0hi.x, a0hi.y, a0hi.z, a0hi.w};
            float a1v[8] = {a1lo.x, a1lo.y, a1lo.z, a1lo.w,
                            a1hi.x, a1hi.y, a1hi.z, a1hi.w};
#pragma unroll
            for (int i = 0; i < 8; i++) {
                acc[i][0][0] = fmaf(a0v[i], b0.x, acc[i][0][0]);
                acc[i][1][0] = fmaf(a0v[i], b0.y, acc[i][1][0]);
                acc[i][0][1] = fmaf(a1v[i], b1.x, acc[i][0][1]);
                acc[i][1][1] = fmaf(a1v[i], b1.y, acc[i][1][1]);
            }
        }
    }

    float w00 = w_fs[0], w01 = w_fs[1], w10 = w_fs[2], w11 = w_fs[3];
    const float* sar_b0 = sar + (size_t)(b * 2 + 0) * H_ * W_;
    const float* sar_b1 = sar + (size_t)(b * 2 + 1) * H_ * W_;
#pragma unroll
    for (int i = 0; i < 8; i++) {
        int h = h0 + rb + i;
#pragma unroll
        for (int j = 0; j < 2; j++) {
            int w = wh * 64 + wt0 + j;
            size_t off = (size_t)h * W_ + w;
            float m0 = acc[i][j][0] + rgb_b0[off];
            float m1 = acc[i][j][1] + rgb_b1[off];
            float fs0 = w00 * m0 + w01 * m1;
            float fs1 = w10 * m0 + w11 * m1;
            g_xpad4[((size_t)b * HP + (h + 1)) * WP + (w + 1)] =
                make_float4(sar_b0[off], sar_b1[off], fs0, fs1);
        }
    }
}

// ---------------------------------------------------------------------------
// Kernel C v6: smem fast-path for bilinear gathers (unbenched; resubmitted).
// Block 256 thr = 128 x * 2 ygrp, 4 output rows/block, grid (H/4, B).
// Tile = 9 padded rows [h0-1 .. h0+7] (clamped at stage) = 18.7KB.
// A sampling point whose y0,y1 both fall in the tile reads all 4 corners
// from smem (immune to cache-line scatter); rare outliers go to global.
// ---------------------------------------------------------------------------
__global__ void __launch_bounds__(256, 3)
deform_kernel(const float* __restrict__ wp, const float* __restrict__ bp,
              const float* __restrict__ wdc, float* __restrict__ out) {
    __shared__ float4 s_tile[9 * WP];     // tile row ry = global y (h0-1+ry)
    __shared__ float4 s_wp4[9 * 18];      // [tap][j] float4 over c_in
    __shared__ float4 s_wdc4[2 * 9];      // [o][n]   float4 over c_in
    __shared__ float  s_bp[18];

    int h0 = blockIdx.x * 4;
    int b  = blockIdx.y;
    int t  = threadIdx.x;
    int ylo_t = h0 - 1;                   // tile origin (global padded y)

    if (t < 18) s_bp[t] = bp[t];
    for (int i = t; i < 9 * 18 * 4; i += 256) {
        int c = i & 3, rest = i >> 2;
        int j = rest % 18, tap = rest / 18;
        ((float*)s_wp4)[i] = wp[(j * 4 + c) * 9 + tap];
    }
    for (int i = t; i < 2 * 9 * 4; i += 256) {
        int c = i & 3, rest = i >> 2;
        int n = rest % 9, o = rest / 9;
        ((float*)s_wdc4)[i] = wdc[(o * 4 + c) * 9 + n];
    }
    const float4* base = g_xpad4 + (size_t)b * HP * WP;
    for (int i = t; i < 9 * WP; i += 256) {
        int ry = i / WP, x = i - ry * WP;
        int gy = min(max(ylo_t + ry, 0), HP - 1);
        s_tile[i] = base[(size_t)gy * WP + x];
    }
    __syncthreads();

    int lane = t & 31;
    int wid  = t >> 5;
    int xc   = (wid & 3) * 32 + lane;   // x in 0..127 (lanes consecutive in x)
    int yg   = wid >> 2;                // 0/1 row-pair group
    int rp   = yg * 2;                  // first output row (within block) of pair

    // ---- offset conv for 2 vertical pixels; off[p][0..8]=dy, [9..17]=dx ----
    float off[2][18];
#pragma unroll
    for (int p = 0; p < 2; p++)
#pragma unroll
        for (int j = 0; j < 18; j++) off[p][j] = s_bp[j];

#pragma unroll
    for (int kx = 0; kx < 3; kx++) {
        float4 v[4];
#pragma unroll
        for (int q = 0; q < 4; q++)
            v[q] = s_tile[(rp + 1 + q) * WP + xc + kx];
#pragma unroll
        for (int ky = 0; ky < 3; ky++) {
            const float4* wr = s_wp4 + (ky * 3 + kx) * 18;
#pragma unroll
            for (int j = 0; j < 18; j++) {
                float4 u = wr[j];
#pragma unroll
                for (int p = 0; p < 2; p++) {
                    float4 vv = v[p + ky];
                    off[p][j] += vv.x * u.x + vv.y * u.y + vv.z * u.z + vv.w * u.w;
                }
            }
        }
    }

    // ---- bilinear sampling + deform-conv reduce, per pixel ----
    float pxb = (float)(xc + 1);
    float* out_b0 = out + (size_t)(b * 2 + 0) * H_ * W_ + xc;
    float* out_b1 = out + (size_t)(b * 2 + 1) * H_ * W_ + xc;
#pragma unroll
    for (int p = 0; p < 2; p++) {
        int h = h0 + rp + p;
        float pyb = (float)(h + 1);
        float acc0 = 0.f, acc1 = 0.f;
#pragma unroll
        for (int n = 0; n < 9; n++) {
            float py = pyb + (float)(n / 3 - 1) + off[p][n];
            float px = pxb + (float)(n % 3 - 1) + off[p][9 + n];
            float fy = floorf(py), fx = floorf(px);
            float y0f = fminf(fmaxf(fy,        0.f), (float)(HP - 1));
            float y1f = fminf(fmaxf(fy + 1.f,  0.f), (float)(HP - 1));
            float x0f = fminf(fmaxf(fx,        0.f), (float)(WP - 1));
            float x1f = fminf(fmaxf(fx + 1.f,  0.f), (float)(WP - 1));
            int y0 = (int)y0f, y1 = (int)y1f, x0 = (int)x0f, x1 = (int)x1f;
            float pyc = fminf(fmaxf(py, 0.f), (float)(HP - 1));
            float pxc = fminf(fmaxf(px, 0.f), (float)(WP - 1));
            float wy0 = 1.f + (y0f - pyc);
            float wy1 = 1.f - (y1f - pyc);
            float wx0 = 1.f + (x0f - pxc);
            float wx1 = 1.f - (x1f - pxc);
            float glt = wy0 * wx0, grb = wy1 * wx1;
            float glb = wy0 * wx1, grt = wy1 * wx0;

            int idx0 = y0 - ylo_t;
            int idx1 = y1 - ylo_t;
            float4 vlt, vrb, vlb, vrt;
            if (((unsigned)idx0 <= 8u) && ((unsigned)idx1 <= 8u)) {
                // fast path: all four corners in the staged tile
                vlt = s_tile[idx0 * WP + x0];
                vlb = s_tile[idx0 * WP + x1];
                vrt = s_tile[idx1 * WP + x0];
                vrb = s_tile[idx1 * WP + x1];
            } else {
                vlt = base[(size_t)y0 * WP + x0];
                vrb = base[(size_t)y1 * WP + x1];
                vlb = base[(size_t)y0 * WP + x1];
                vrt = base[(size_t)y1 * WP + x0];
            }

            float4 s;
            s.x = glt * vlt.x + grb * vrb.x + glb * vlb.x + grt * vrt.x;
            s.y = glt * vlt.y + grb * vrb.y + glb * vlb.y + grt * vrt.y;
            s.z = glt * vlt.z + grb * vrb.z + glb * vlb.z + grt * vrt.z;
            s.w = glt * vlt.w + grb * vrb.w + glb * vlb.w + grt * vrt.w;

            float4 wa = s_wdc4[n];
            float4 wb = s_wdc4[9 + n];
            acc0 += s.x * wa.x + s.y * wa.y + s.z * wa.z + s.w * wa.w;
            acc1 += s.x * wb.x + s.y * wb.y + s.z * wb.z + s.w * wb.w;
        }
        out_b0[(size_t)h * W_] = acc0;
        out_b1[(size_t)h * W_] = acc1;
    }
}

// ---------------------------------------------------------------------------
extern "C" void kernel_launch(void* const* d_in, const int* in_sizes, int n_in,
                              void* d_out, int out_size) {
    const float* rgb  = (const float*)d_in[0];
    const float* sar  = (const float*)d_in[1];
    const float* w_fm = (const float*)d_in[2];
    const float* w_fs = (const float*)d_in[3];
    const float* w_p  = (const float*)d_in[4];
    const float* b_p  = (const float*)d_in[5];
    const float* w_dc = (const float*)d_in[6];
    float* out = (float*)d_out;

    {
        int total = B_ * (2 * WP + 2 * HP);
        border_kernel<<<(total + 255) / 256, 256>>>();
    }
    fm_kernel<<<(NPIX + 255) / 256, 256>>>(rgb, w_fm);
    {
        int smem = (16384 + 2 * KT * R_PAD) * (int)sizeof(float);
        cudaFuncSetAttribute(fs_kernel,
                             cudaFuncAttributeMaxDynamicSharedMemorySize, smem);
        dim3 grid(H_ / 64, 2, B_);
        fs_kernel<<<grid, 256, smem>>>(rgb, sar, w_fs);
    }
    {
        dim3 grid(H_ / 4, B_);
        deform_kernel<<<grid, 256>>>(w_p, b_p, w_dc, out);
    }
}